// round 11
// baseline (speedup 1.0000x reference)
#include <cuda_runtime.h>
#include <cuda_bf16.h>
#include <cstdint>

// LogSignature depth=4 of path (B=128, T=512, C=8).
// Output per batch: [L1(8) | L2(64) | L3(512) | L4(4096)] = 4680 floats.
//
// ROUND 11: k-half ownership. One CTA per batch, 512 threads =
// 64 (i,j) x 2 k-halves x 4 time segments (128 steps each, scalar fp32).
// Thread (ij, kh, s) carries r1(i), r2(ij) [replicated], r3[4] and
// a[4][8] = L4 rows k in [4kh,4kh+4) for its segment. Per step:
//   didj, r1dj, ng, n2                     (7)
//   g[kk]=r3+ng*dk; r3+=n2*dk              (8)
//   a[kk][l] += g[kk]*d[l]                 (32)
//   r2 += r1dj + 0.5*didj; r1 += di        (3)
// = 50 FMA per 4 ijk-rows (vs 21/row in the ijk-per-thread layout).
// Segments combine with a 2-round shfl-xor Chen tree (L4 in registers,
// levels<=3 via smem), then closed-form truncated log.

#define BATCH 128
#define TLEN  512
#define CH    8
#define NSTEP (TLEN - 1)     // 511
#define NSEG  4
#define SEGLEN 128           // seg 3: 127 real steps + 1 zero pad
#define OUT_STRIDE 4680
#define OFF_L2 8
#define OFF_L3 72
#define OFF_L4 584

#define C3F (1.0f / 6.0f)
#define C4F (1.0f / 24.0f)

__global__ void __launch_bounds__(512, 1)
logsig_kernel(const float* __restrict__ path, float* __restrict__ out)
{
    __shared__ __align__(16) float s_dx[TLEN * CH];   // 16 KB; slot 511 zeroed
    __shared__ __align__(16) float sL[NSEG][584];     // per-segment-group levels 1..3

    const int b   = blockIdx.x;
    const int tid = threadIdx.x;
    const float* p = path + (size_t)b * TLEN * CH;

    // increments (slots >= NSTEP zero -> exp(0) = identity pad)
    for (int idx = tid; idx < TLEN * CH; idx += 512) {
        float v = 0.0f;
        if (idx < NSTEP * CH) v = p[idx + CH] - p[idx];
        s_dx[idx] = v;
    }
    __syncthreads();

    const int s  = tid & 3;            // segment (lane bits 0..1 -> shfl-xor tree)
    const int kh = (tid >> 2) & 1;     // k half
    const int ij = tid >> 3;           // 0..63
    const int i  = ij >> 3;
    const int j  = ij & 7;
    const int k0 = kh << 2;            // first owned k row

    float a[4][8];
    float r3[4];
    float r1 = 0.0f, r2 = 0.0f;
    #pragma unroll
    for (int kk = 0; kk < 4; ++kk) {
        r3[kk] = 0.0f;
        #pragma unroll
        for (int l = 0; l < 8; ++l) a[kk][l] = 0.0f;
    }

    // ---- scan own segment ----
    {
        const float* d = &s_dx[s * SEGLEN * CH];
        #pragma unroll 1
        for (int t = 0; t < SEGLEN; ++t, d += CH) {
            const float4 dlo = *(const float4*)(d);
            const float4 dhi = *(const float4*)(d + 4);
            const float4 dk4 = *(const float4*)(d + k0);   // own 4 k values
            const float dv[8] = {dlo.x, dlo.y, dlo.z, dlo.w,
                                 dhi.x, dhi.y, dhi.z, dhi.w};
            const float di = d[i];
            const float dj = d[j];

            const float didj = di * dj;
            const float r1dj = r1 * dj;

            float ng = 0.5f * r2;              // c2 r2 + c3 r1dj + c4 didj
            ng = fmaf(C3F, r1dj, ng);
            ng = fmaf(C4F, didj, ng);
            float n2 = fmaf(0.5f, r1dj, r2);   // r2 + c2 r1dj + c3 didj
            n2 = fmaf(C3F, didj, n2);

            float g0 = fmaf(ng, dk4.x, r3[0]);  r3[0] = fmaf(n2, dk4.x, r3[0]);
            float g1 = fmaf(ng, dk4.y, r3[1]);  r3[1] = fmaf(n2, dk4.y, r3[1]);
            float g2 = fmaf(ng, dk4.z, r3[2]);  r3[2] = fmaf(n2, dk4.z, r3[2]);
            float g3 = fmaf(ng, dk4.w, r3[3]);  r3[3] = fmaf(n2, dk4.w, r3[3]);

            #pragma unroll
            for (int l = 0; l < 8; ++l) {
                a[0][l] = fmaf(g0, dv[l], a[0][l]);
                a[1][l] = fmaf(g1, dv[l], a[1][l]);
                a[2][l] = fmaf(g2, dv[l], a[2][l]);
                a[3][l] = fmaf(g3, dv[l], a[3][l]);
            }

            r2 = fmaf(0.5f, didj, r1dj) + r2;
            r1 += di;
        }
    }

    // ---- publish own segment levels 1..3 ----
    auto publish = [&](void) {
        #pragma unroll
        for (int kk = 0; kk < 4; ++kk) sL[s][72 + ij * 8 + k0 + kk] = r3[kk];
        sL[s][8 + ij] = r2;                 // both kh write identical value
        if (j == 0 && kh == 0) sL[s][i] = r1;
    };
    publish();
    __syncthreads();

    // ---- 2-round Chen combine tree over segments ----
    #pragma unroll 1
    for (int r = 0; r < 2; ++r) {
        const int blk   = 1 << r;
        const int Abase = s & ~((blk << 1) - 1);
        const int Bbase = Abase + blk;
        const float* LA = sL[Abase];
        const float* LB = sL[Bbase];

        const float A1 = LA[i];
        const float A2 = LA[8 + ij];
        float A3k[4];
        #pragma unroll
        for (int kk = 0; kk < 4; ++kk) A3k[kk] = LA[72 + ij * 8 + k0 + kk];

        const float c1  = A1 + LB[i];
        const float c2v = A2 + LB[8 + ij] + A1 * LB[j];

        float c3[4];
        #pragma unroll
        for (int kk = 0; kk < 4; ++kk) {
            const int k = k0 + kk;
            float t = A3k[kk] + LB[72 + ij * 8 + k];
            t = fmaf(A1, LB[8 + j * 8 + k], t);
            t = fmaf(A2, LB[k], t);
            c3[kk] = t;
        }

        const float4 b1lo = *(const float4*)(&LB[0]);
        const float4 b1hi = *(const float4*)(&LB[4]);
        const float b1[8] = {b1lo.x, b1lo.y, b1lo.z, b1lo.w,
                             b1hi.x, b1hi.y, b1hi.z, b1hi.w};

        #pragma unroll
        for (int kk = 0; kk < 4; ++kk) {
            const int k = k0 + kk;
            const float4 b3lo = *(const float4*)(&LB[72 + (j * 8 + k) * 8]);
            const float4 b3hi = *(const float4*)(&LB[72 + (j * 8 + k) * 8 + 4]);
            const float4 b2lo = *(const float4*)(&LB[8 + k * 8]);
            const float4 b2hi = *(const float4*)(&LB[8 + k * 8 + 4]);
            const float b3r[8] = {b3lo.x, b3lo.y, b3lo.z, b3lo.w,
                                  b3hi.x, b3hi.y, b3hi.z, b3hi.w};
            const float b2r[8] = {b2lo.x, b2lo.y, b2lo.z, b2lo.w,
                                  b2hi.x, b2hi.y, b2hi.z, b2hi.w};
            #pragma unroll
            for (int l = 0; l < 8; ++l) {
                float t = a[kk][l] + __shfl_xor_sync(0xffffffffu, a[kk][l], blk);
                t = fmaf(A1, b3r[l], t);
                t = fmaf(A2, b2r[l], t);
                t = fmaf(A3k[kk], b1[l], t);
                a[kk][l] = t;
            }
        }

        r1 = c1;
        r2 = c2v;
        #pragma unroll
        for (int kk = 0; kk < 4; ++kk) r3[kk] = c3[kk];

        __syncthreads();       // all reads of sL done
        publish();
        __syncthreads();
    }

    // ---- closed-form log(1+x) truncated at depth 4 ----
    const float* L = sL[0];    // final combined levels (all slots identical)
    const float4 v1lo = *(const float4*)(&L[0]);
    const float4 v1hi = *(const float4*)(&L[4]);
    const float v1[8] = {v1lo.x, v1lo.y, v1lo.z, v1lo.w,
                         v1hi.x, v1hi.y, v1hi.z, v1hi.w};
    const float si = v1[i];
    const float sj = v1[j];
    const float sisj = si * sj;
    const float Q = fmaf(1.0f / 3.0f, sisj, -0.5f * r2);
    const float R = -0.5f * si;

    float* ob = out + (size_t)b * OUT_STRIDE;

    #pragma unroll
    for (int kk = 0; kk < 4; ++kk) {
        const int k = k0 + kk;
        const float sk = v1[k];
        const float s2jk = L[8 + j * 8 + k];
        const float cross = fmaf(si, s2jk, r2 * sk);
        const float sss = sisj * sk;
        const float P = fmaf(1.0f / 3.0f, cross, -0.5f * r3[kk]) - 0.25f * sss;
        const float o3 = fmaf(1.0f / 3.0f, sss, fmaf(-0.5f, cross, r3[kk]));

        const float4 s3lo = *(const float4*)(&L[72 + (j * 8 + k) * 8]);
        const float4 s3hi = *(const float4*)(&L[72 + (j * 8 + k) * 8 + 4]);
        const float4 s2lo = *(const float4*)(&L[8 + k * 8]);
        const float4 s2hi = *(const float4*)(&L[8 + k * 8 + 4]);
        const float s3r[8] = {s3lo.x, s3lo.y, s3lo.z, s3lo.w,
                              s3hi.x, s3hi.y, s3hi.z, s3hi.w};
        const float s2r[8] = {s2lo.x, s2lo.y, s2lo.z, s2lo.w,
                              s2hi.x, s2hi.y, s2hi.z, s2hi.w};
        #pragma unroll
        for (int l = 0; l < 8; ++l) {
            float t = fmaf(P, v1[l], a[kk][l]);
            t = fmaf(Q, s2r[l], t);
            t = fmaf(R, s3r[l], t);
            a[kk][l] = t;
        }

        // replica s stores row kk == s (4 replicas cover the 4 owned rows)
        if (kk == s) {
            float4 w0 = {a[kk][0], a[kk][1], a[kk][2], a[kk][3]};
            float4 w1 = {a[kk][4], a[kk][5], a[kk][6], a[kk][7]};
            *(float4*)(&ob[OFF_L4 + (ij * 8 + k) * 8])     = w0;
            *(float4*)(&ob[OFF_L4 + (ij * 8 + k) * 8 + 4]) = w1;
            ob[OFF_L3 + ij * 8 + k] = o3;
        }
    }

    if (s == 0 && kh == 0)
        ob[OFF_L2 + ij] = fmaf(-0.5f, sisj, r2);
    if (s == 0 && kh == 0 && j == 0)
        ob[i] = r1;
}

extern "C" void kernel_launch(void* const* d_in, const int* in_sizes, int n_in,
                              void* d_out, int out_size)
{
    const float* path = (const float*)d_in[0];
    float* out = (float*)d_out;
    logsig_kernel<<<BATCH, 512>>>(path, out);
}

// round 12
// speedup vs baseline: 2.2210x; 2.2210x over previous
#include <cuda_runtime.h>
#include <cuda_bf16.h>
#include <cstdint>

// LogSignature depth=4 of path (B=128, T=512, C=8).
// Output per batch: [L1(8) | L2(64) | L3(512) | L4(4096)] = 4680 floats.
//
// ROUND 12: R11 (i,j,k-half) ownership, fixed:
//  * segments padded (+4 floats) in shared -> distinct bank regions,
//    killing the 4-way LDS conflicts that made R11 L1-bound (76.5%).
//  * L4 update packed over l-pairs: 16 FFMA2 (rt==scalar FFMA, 2x lanes).
// 512 threads = 64 (i,j) x 2 k-halves x 4 segments (128 steps).
// Per step/thread (~44 issued instr for 4 ijk-rows):
//   2 LDS.128 (d row as 4 u64 pairs) + 2 LDS.32 (di,dj)
//   aux: didj,r1dj,ng(3),n2(2)                      scalar
//   g[kk]=fma(ng,dk,r3); r3+=n2*dk  (dk unpacked from pairs)
//   a2[kk][lp] += (g,g)*(d2l,d2l+1)   16 FFMA2 = 64 lanes
//   r2,r1 updates
// 2-round shfl-xor Chen tree (packed), closed-form log (packed).

#define BATCH 128
#define TLEN  512
#define CH    8
#define NSTEP (TLEN - 1)     // 511
#define NSEG  4
#define SEGLEN 128           // seg 3: 127 real steps + 1 zero pad
#define SEGSZ  (SEGLEN * CH + 4)   // padded floats per segment (16B shift)
#define OUT_STRIDE 4680
#define OFF_L2 8
#define OFF_L3 72
#define OFF_L4 584

#define C3F (1.0f / 6.0f)
#define C4F (1.0f / 24.0f)

typedef unsigned long long u64;

#define FFMA2_ACC(acc, a, b) \
    asm("fma.rn.f32x2 %0, %1, %2, %0;" : "+l"(acc) : "l"(a), "l"(b))
#define FADD2_ACC(acc, a) \
    asm("add.rn.f32x2 %0, %0, %1;" : "+l"(acc) : "l"(a))

__device__ __forceinline__ u64 pack2(float x, float y) {
    u64 d; asm("mov.b64 %0, {%1, %2};" : "=l"(d) : "f"(x), "f"(y)); return d;
}
__device__ __forceinline__ void unpack2(u64 a, float& x, float& y) {
    asm("mov.b64 {%0, %1}, %2;" : "=f"(x), "=f"(y) : "l"(a));
}

__global__ void __launch_bounds__(512, 1)
logsig_kernel(const float* __restrict__ path, float* __restrict__ out)
{
    __shared__ __align__(16) float s_dx[NSEG * SEGSZ];   // ~16.4 KB padded
    __shared__ __align__(16) float sL[NSEG][584];        // per-seg levels 1..3

    const int b   = blockIdx.x;
    const int tid = threadIdx.x;
    const float* p = path + (size_t)b * TLEN * CH;

    // increments into padded layout (global step 511 zero-padded)
    for (int idx = tid; idx < NSEG * SEGLEN * CH; idx += 512) {
        const int t = idx >> 3;            // global step
        const int c = idx & 7;
        float v = 0.0f;
        if (t < NSTEP) v = p[idx + CH] - p[idx];
        s_dx[(t >> 7) * SEGSZ + (t & 127) * CH + c] = v;
    }
    __syncthreads();

    const int s  = tid & 3;            // segment (lane bits 0..1: shfl tree)
    const int kh = (tid >> 2) & 1;     // k half
    const int ij = tid >> 3;           // 0..63
    const int i  = ij >> 3;
    const int j  = ij & 7;
    const int k0 = kh << 2;            // first owned k row

    u64 a2[4][4];                      // L4 rows k0..k0+3, l packed in pairs
    float r3[4];
    float r1 = 0.0f, r2 = 0.0f;
    #pragma unroll
    for (int kk = 0; kk < 4; ++kk) {
        r3[kk] = 0.0f;
        #pragma unroll
        for (int lp = 0; lp < 4; ++lp) a2[kk][lp] = 0;
    }

    // ---- scan own segment ----
    {
        const float* d = &s_dx[s * SEGSZ];
        #pragma unroll 1
        for (int t = 0; t < SEGLEN; ++t, d += CH) {
            const ulonglong2 qa = *(const ulonglong2*)(d);      // (d0,d1),(d2,d3)
            const ulonglong2 qb = *(const ulonglong2*)(d + 4);  // (d4,d5),(d6,d7)
            const float di = d[i];
            const float dj = d[j];

            const float didj = di * dj;
            const float r1dj = r1 * dj;

            float ng = 0.5f * r2;
            ng = fmaf(C3F, r1dj, ng);
            ng = fmaf(C4F, didj, ng);
            float n2 = fmaf(0.5f, r1dj, r2);
            n2 = fmaf(C3F, didj, n2);

            // own 4 dk values come from the already-loaded pairs
            float dk0v, dk1v, dk2v, dk3v;
            if (kh == 0) { unpack2(qa.x, dk0v, dk1v); unpack2(qa.y, dk2v, dk3v); }
            else         { unpack2(qb.x, dk0v, dk1v); unpack2(qb.y, dk2v, dk3v); }

            const float g0 = fmaf(ng, dk0v, r3[0]);  r3[0] = fmaf(n2, dk0v, r3[0]);
            const float g1 = fmaf(ng, dk1v, r3[1]);  r3[1] = fmaf(n2, dk1v, r3[1]);
            const float g2v = fmaf(ng, dk2v, r3[2]); r3[2] = fmaf(n2, dk2v, r3[2]);
            const float g3 = fmaf(ng, dk3v, r3[3]);  r3[3] = fmaf(n2, dk3v, r3[3]);

            const u64 G0 = pack2(g0, g0);
            const u64 G1 = pack2(g1, g1);
            const u64 G2 = pack2(g2v, g2v);
            const u64 G3 = pack2(g3, g3);

            FFMA2_ACC(a2[0][0], G0, qa.x);  FFMA2_ACC(a2[0][1], G0, qa.y);
            FFMA2_ACC(a2[0][2], G0, qb.x);  FFMA2_ACC(a2[0][3], G0, qb.y);
            FFMA2_ACC(a2[1][0], G1, qa.x);  FFMA2_ACC(a2[1][1], G1, qa.y);
            FFMA2_ACC(a2[1][2], G1, qb.x);  FFMA2_ACC(a2[1][3], G1, qb.y);
            FFMA2_ACC(a2[2][0], G2, qa.x);  FFMA2_ACC(a2[2][1], G2, qa.y);
            FFMA2_ACC(a2[2][2], G2, qb.x);  FFMA2_ACC(a2[2][3], G2, qb.y);
            FFMA2_ACC(a2[3][0], G3, qa.x);  FFMA2_ACC(a2[3][1], G3, qa.y);
            FFMA2_ACC(a2[3][2], G3, qb.x);  FFMA2_ACC(a2[3][3], G3, qb.y);

            r2 = fmaf(0.5f, didj, r1dj) + r2;
            r1 += di;
        }
    }

    // ---- publish own segment levels 1..3 ----
    auto publish = [&](void) {
        #pragma unroll
        for (int kk = 0; kk < 4; ++kk) sL[s][72 + ij * 8 + k0 + kk] = r3[kk];
        if (kh == 0) sL[s][8 + ij] = r2;
        if (j == 0 && kh == 0) sL[s][i] = r1;
    };
    publish();
    __syncthreads();

    // ---- 2-round Chen combine tree over segments ----
    #pragma unroll 1
    for (int r = 0; r < 2; ++r) {
        const int blk   = 1 << r;
        const int Abase = s & ~((blk << 1) - 1);
        const int Bbase = Abase + blk;
        const float* LA = sL[Abase];
        const float* LB = sL[Bbase];

        const float A1 = LA[i];
        const float A2 = LA[8 + ij];
        float A3k[4];
        #pragma unroll
        for (int kk = 0; kk < 4; ++kk) A3k[kk] = LA[72 + ij * 8 + k0 + kk];

        const float c1  = A1 + LB[i];
        const float c2v = A2 + LB[8 + ij] + A1 * LB[j];

        float c3[4];
        #pragma unroll
        for (int kk = 0; kk < 4; ++kk) {
            const int k = k0 + kk;
            float t = A3k[kk] + LB[72 + ij * 8 + k];
            t = fmaf(A1, LB[8 + j * 8 + k], t);
            t = fmaf(A2, LB[k], t);
            c3[kk] = t;
        }

        const u64 A1d = pack2(A1, A1);
        const u64 A2d = pack2(A2, A2);
        const u64* b1p = (const u64*)&LB[0];

        #pragma unroll
        for (int kk = 0; kk < 4; ++kk) {
            const int k = k0 + kk;
            const u64* b3p = (const u64*)&LB[72 + (j * 8 + k) * 8];
            const u64* b2p = (const u64*)&LB[8 + k * 8];
            const u64 A3d = pack2(A3k[kk], A3k[kk]);
            #pragma unroll
            for (int lp = 0; lp < 4; ++lp) {
                u64 t = a2[kk][lp];
                const u64 part = __shfl_xor_sync(0xffffffffu, t, blk);
                FADD2_ACC(t, part);
                FFMA2_ACC(t, A1d, b3p[lp]);
                FFMA2_ACC(t, A2d, b2p[lp]);
                FFMA2_ACC(t, A3d, b1p[lp]);
                a2[kk][lp] = t;
            }
        }

        r1 = c1;
        r2 = c2v;
        #pragma unroll
        for (int kk = 0; kk < 4; ++kk) r3[kk] = c3[kk];

        __syncthreads();
        publish();
        __syncthreads();
    }

    // ---- closed-form log(1+x) truncated at depth 4 ----
    const float* L = sL[0];                 // final combined (all slots equal)
    const u64* v12 = (const u64*)L;         // L1 as packed pairs
    const float si = L[i];
    const float sj = L[j];
    const float sisj = si * sj;
    const float Qs = fmaf(1.0f / 3.0f, sisj, -0.5f * r2);
    const float Rs = -0.5f * si;
    const u64 Q2 = pack2(Qs, Qs);
    const u64 R2 = pack2(Rs, Rs);

    float* ob = out + (size_t)b * OUT_STRIDE;

    #pragma unroll
    for (int kk = 0; kk < 4; ++kk) {
        const int k = k0 + kk;
        const float sk = L[k];
        const float s2jk = L[8 + j * 8 + k];
        const float cross = fmaf(si, s2jk, r2 * sk);
        const float sss = sisj * sk;
        const float P = fmaf(1.0f / 3.0f, cross, -0.5f * r3[kk]) - 0.25f * sss;
        const float o3 = fmaf(1.0f / 3.0f, sss, fmaf(-0.5f, cross, r3[kk]));
        const u64 P2 = pack2(P, P);

        const u64* s2p = (const u64*)&L[8 + k * 8];
        const u64* s3p = (const u64*)&L[72 + (j * 8 + k) * 8];

        u64 ov[4];
        #pragma unroll
        for (int lp = 0; lp < 4; ++lp) {
            u64 t = a2[kk][lp];
            FFMA2_ACC(t, P2, v12[lp]);
            FFMA2_ACC(t, Q2, s2p[lp]);
            FFMA2_ACC(t, R2, s3p[lp]);
            ov[lp] = t;
        }

        if (kk == s) {          // replica s stores its matching row
            ulonglong2 w0 = {ov[0], ov[1]};
            ulonglong2 w1 = {ov[2], ov[3]};
            *(ulonglong2*)(&ob[OFF_L4 + (ij * 8 + k) * 8])     = w0;
            *(ulonglong2*)(&ob[OFF_L4 + (ij * 8 + k) * 8 + 4]) = w1;
            ob[OFF_L3 + ij * 8 + k] = o3;
        }
    }

    if (s == 0 && kh == 0)
        ob[OFF_L2 + ij] = fmaf(-0.5f, sisj, r2);
    if (s == 0 && kh == 0 && j == 0)
        ob[i] = r1;
}

extern "C" void kernel_launch(void* const* d_in, const int* in_sizes, int n_in,
                              void* d_out, int out_size)
{
    const float* path = (const float*)d_in[0];
    float* out = (float*)d_out;
    logsig_kernel<<<BATCH, 512>>>(path, out);
}

// round 13
// speedup vs baseline: 2.2461x; 1.0113x over previous
#include <cuda_runtime.h>
#include <cuda_bf16.h>
#include <cstdint>

// LogSignature depth=4 of path (B=128, T=512, C=8).
// Output per batch: [L1(8) | L2(64) | L3(512) | L4(4096)] = 4680 floats.
//
// ROUND 13: R12 + three fixes:
//  * dk4 loaded directly as float4 (one LDS.128) -> kills the kh-predicated
//    unpack SEL/MOVs that showed up as alu=18.9%.
//  * SEGSZ pad 1028->1032 floats: all 8 (s,kh) load addresses distinct mod
//    128B -> fully conflict-free LDS.
//  * prefetch next iteration's di/dj/dk4 (critical g-path); the 8-float
//    segment pad absorbs the final over-read.
// Layout unchanged: 512 thr = 64 (i,j) x 2 k-halves x 4 segments(128 steps).

#define BATCH 128
#define TLEN  512
#define CH    8
#define NSTEP (TLEN - 1)     // 511
#define NSEG  4
#define SEGLEN 128           // seg 3: 127 real steps + 1 zero pad
#define SEGSZ  (SEGLEN * CH + 8)   // 1032 floats; pad also absorbs prefetch
#define OUT_STRIDE 4680
#define OFF_L2 8
#define OFF_L3 72
#define OFF_L4 584

#define C3F (1.0f / 6.0f)
#define C4F (1.0f / 24.0f)

typedef unsigned long long u64;

#define FFMA2_ACC(acc, a, b) \
    asm("fma.rn.f32x2 %0, %1, %2, %0;" : "+l"(acc) : "l"(a), "l"(b))
#define FADD2_ACC(acc, a) \
    asm("add.rn.f32x2 %0, %0, %1;" : "+l"(acc) : "l"(a))

__device__ __forceinline__ u64 pack2(float x, float y) {
    u64 d; asm("mov.b64 %0, {%1, %2};" : "=l"(d) : "f"(x), "f"(y)); return d;
}

__global__ void __launch_bounds__(512, 1)
logsig_kernel(const float* __restrict__ path, float* __restrict__ out)
{
    __shared__ __align__(16) float s_dx[NSEG * SEGSZ];   // ~16.5 KB padded
    __shared__ __align__(16) float sL[NSEG][584];        // per-seg levels 1..3

    const int b   = blockIdx.x;
    const int tid = threadIdx.x;
    const float* p = path + (size_t)b * TLEN * CH;

    // zero the 4 segment pads (8 floats each)
    if (tid < 32)
        s_dx[(tid >> 3) * SEGSZ + SEGLEN * CH + (tid & 7)] = 0.0f;
    // increments into padded layout (global step 511 zero-padded)
    for (int idx = tid; idx < NSEG * SEGLEN * CH; idx += 512) {
        const int t = idx >> 3;            // global step
        const int c = idx & 7;
        float v = 0.0f;
        if (t < NSTEP) v = p[idx + CH] - p[idx];
        s_dx[(t >> 7) * SEGSZ + (t & 127) * CH + c] = v;
    }
    __syncthreads();

    const int s  = tid & 3;            // segment (lane bits 0..1: shfl tree)
    const int kh = (tid >> 2) & 1;     // k half
    const int ij = tid >> 3;           // 0..63
    const int i  = ij >> 3;
    const int j  = ij & 7;
    const int k0 = kh << 2;            // first owned k row

    u64 a2[4][4];                      // L4 rows k0..k0+3, l packed in pairs
    float r3[4];
    float r1 = 0.0f, r2 = 0.0f;
    #pragma unroll
    for (int kk = 0; kk < 4; ++kk) {
        r3[kk] = 0.0f;
        #pragma unroll
        for (int lp = 0; lp < 4; ++lp) a2[kk][lp] = 0;
    }

    // ---- scan own segment (prefetched critical-path loads) ----
    {
        const float* d = &s_dx[s * SEGSZ];
        float4 dk4 = *(const float4*)(d + k0);
        float di = d[i];
        float dj = d[j];

        #pragma unroll 1
        for (int t = 0; t < SEGLEN; ++t, d += CH) {
            const ulonglong2 qa = *(const ulonglong2*)(d);      // l pairs 0-3
            const ulonglong2 qb = *(const ulonglong2*)(d + 4);  // l pairs 4-7

            // prefetch next row's critical values (pad absorbs last over-read)
            const float4 ndk4 = *(const float4*)(d + CH + k0);
            const float ndi = d[CH + i];
            const float ndj = d[CH + j];

            const float didj = di * dj;
            const float r1dj = r1 * dj;

            float ng = 0.5f * r2;
            ng = fmaf(C3F, r1dj, ng);
            ng = fmaf(C4F, didj, ng);
            float n2 = fmaf(0.5f, r1dj, r2);
            n2 = fmaf(C3F, didj, n2);

            const float g0 = fmaf(ng, dk4.x, r3[0]);  r3[0] = fmaf(n2, dk4.x, r3[0]);
            const float g1 = fmaf(ng, dk4.y, r3[1]);  r3[1] = fmaf(n2, dk4.y, r3[1]);
            const float g2v = fmaf(ng, dk4.z, r3[2]); r3[2] = fmaf(n2, dk4.z, r3[2]);
            const float g3 = fmaf(ng, dk4.w, r3[3]);  r3[3] = fmaf(n2, dk4.w, r3[3]);

            const u64 G0 = pack2(g0, g0);
            const u64 G1 = pack2(g1, g1);
            const u64 G2 = pack2(g2v, g2v);
            const u64 G3 = pack2(g3, g3);

            FFMA2_ACC(a2[0][0], G0, qa.x);  FFMA2_ACC(a2[0][1], G0, qa.y);
            FFMA2_ACC(a2[0][2], G0, qb.x);  FFMA2_ACC(a2[0][3], G0, qb.y);
            FFMA2_ACC(a2[1][0], G1, qa.x);  FFMA2_ACC(a2[1][1], G1, qa.y);
            FFMA2_ACC(a2[1][2], G1, qb.x);  FFMA2_ACC(a2[1][3], G1, qb.y);
            FFMA2_ACC(a2[2][0], G2, qa.x);  FFMA2_ACC(a2[2][1], G2, qa.y);
            FFMA2_ACC(a2[2][2], G2, qb.x);  FFMA2_ACC(a2[2][3], G2, qb.y);
            FFMA2_ACC(a2[3][0], G3, qa.x);  FFMA2_ACC(a2[3][1], G3, qa.y);
            FFMA2_ACC(a2[3][2], G3, qb.x);  FFMA2_ACC(a2[3][3], G3, qb.y);

            r2 = fmaf(0.5f, didj, r1dj) + r2;
            r1 += di;

            dk4 = ndk4;
            di = ndi;
            dj = ndj;
        }
    }

    // ---- publish own segment levels 1..3 ----
    auto publish = [&](void) {
        #pragma unroll
        for (int kk = 0; kk < 4; ++kk) sL[s][72 + ij * 8 + k0 + kk] = r3[kk];
        if (kh == 0) sL[s][8 + ij] = r2;
        if (j == 0 && kh == 0) sL[s][i] = r1;
    };
    publish();
    __syncthreads();

    // ---- 2-round Chen combine tree over segments ----
    #pragma unroll 1
    for (int r = 0; r < 2; ++r) {
        const int blk   = 1 << r;
        const int Abase = s & ~((blk << 1) - 1);
        const int Bbase = Abase + blk;
        const float* LA = sL[Abase];
        const float* LB = sL[Bbase];

        const float A1 = LA[i];
        const float A2 = LA[8 + ij];
        float A3k[4];
        #pragma unroll
        for (int kk = 0; kk < 4; ++kk) A3k[kk] = LA[72 + ij * 8 + k0 + kk];

        const float c1  = A1 + LB[i];
        const float c2v = A2 + LB[8 + ij] + A1 * LB[j];

        float c3[4];
        #pragma unroll
        for (int kk = 0; kk < 4; ++kk) {
            const int k = k0 + kk;
            float t = A3k[kk] + LB[72 + ij * 8 + k];
            t = fmaf(A1, LB[8 + j * 8 + k], t);
            t = fmaf(A2, LB[k], t);
            c3[kk] = t;
        }

        const u64 A1d = pack2(A1, A1);
        const u64 A2d = pack2(A2, A2);
        const u64* b1p = (const u64*)&LB[0];

        #pragma unroll
        for (int kk = 0; kk < 4; ++kk) {
            const int k = k0 + kk;
            const u64* b3p = (const u64*)&LB[72 + (j * 8 + k) * 8];
            const u64* b2p = (const u64*)&LB[8 + k * 8];
            const u64 A3d = pack2(A3k[kk], A3k[kk]);
            #pragma unroll
            for (int lp = 0; lp < 4; ++lp) {
                u64 t = a2[kk][lp];
                const u64 part = __shfl_xor_sync(0xffffffffu, t, blk);
                FADD2_ACC(t, part);
                FFMA2_ACC(t, A1d, b3p[lp]);
                FFMA2_ACC(t, A2d, b2p[lp]);
                FFMA2_ACC(t, A3d, b1p[lp]);
                a2[kk][lp] = t;
            }
        }

        r1 = c1;
        r2 = c2v;
        #pragma unroll
        for (int kk = 0; kk < 4; ++kk) r3[kk] = c3[kk];

        __syncthreads();
        publish();
        __syncthreads();
    }

    // ---- closed-form log(1+x) truncated at depth 4 ----
    const float* L = sL[0];                 // final combined (all slots equal)
    const u64* v12 = (const u64*)L;         // L1 as packed pairs
    const float si = L[i];
    const float sj = L[j];
    const float sisj = si * sj;
    const float Qs = fmaf(1.0f / 3.0f, sisj, -0.5f * r2);
    const float Rs = -0.5f * si;
    const u64 Q2 = pack2(Qs, Qs);
    const u64 R2 = pack2(Rs, Rs);

    float* ob = out + (size_t)b * OUT_STRIDE;

    #pragma unroll
    for (int kk = 0; kk < 4; ++kk) {
        const int k = k0 + kk;
        const float sk = L[k];
        const float s2jk = L[8 + j * 8 + k];
        const float cross = fmaf(si, s2jk, r2 * sk);
        const float sss = sisj * sk;
        const float P = fmaf(1.0f / 3.0f, cross, -0.5f * r3[kk]) - 0.25f * sss;
        const float o3 = fmaf(1.0f / 3.0f, sss, fmaf(-0.5f, cross, r3[kk]));
        const u64 P2 = pack2(P, P);

        const u64* s2p = (const u64*)&L[8 + k * 8];
        const u64* s3p = (const u64*)&L[72 + (j * 8 + k) * 8];

        u64 ov[4];
        #pragma unroll
        for (int lp = 0; lp < 4; ++lp) {
            u64 t = a2[kk][lp];
            FFMA2_ACC(t, P2, v12[lp]);
            FFMA2_ACC(t, Q2, s2p[lp]);
            FFMA2_ACC(t, R2, s3p[lp]);
            ov[lp] = t;
        }

        if (kk == s) {          // replica s stores its matching row
            ulonglong2 w0 = {ov[0], ov[1]};
            ulonglong2 w1 = {ov[2], ov[3]};
            *(ulonglong2*)(&ob[OFF_L4 + (ij * 8 + k) * 8])     = w0;
            *(ulonglong2*)(&ob[OFF_L4 + (ij * 8 + k) * 8 + 4]) = w1;
            ob[OFF_L3 + ij * 8 + k] = o3;
        }
    }

    if (s == 0 && kh == 0)
        ob[OFF_L2 + ij] = fmaf(-0.5f, sisj, r2);
    if (s == 0 && kh == 0 && j == 0)
        ob[i] = r1;
}

extern "C" void kernel_launch(void* const* d_in, const int* in_sizes, int n_in,
                              void* d_out, int out_size)
{
    const float* path = (const float*)d_in[0];
    float* out = (float*)d_out;
    logsig_kernel<<<BATCH, 512>>>(path, out);
}

// round 14
// speedup vs baseline: 2.2742x; 1.0125x over previous
#include <cuda_runtime.h>
#include <cuda_bf16.h>
#include <cstdint>

// LogSignature depth=4 of path (B=128, T=512, C=8).
// Output per batch: [L1(8) | L2(64) | L3(512) | L4(4096)] = 4680 floats.
//
// ROUND 14: R13 +
//  * dk pairs taken from the already-loaded qa/qb (2 SELs) -> drops the
//    ndk4 LDS.128 (5 -> 4 LDS/iter; L1 was 52%).
//  * g/r3 chain packed as k-pairs: 8 scalar FMA -> 4 FFMA2.
//  * full prefetch of qa/qb/di/dj one iteration ahead: only the short
//    r2->ng chain remains loop-carried.
// Layout: 512 thr = 64 (i,j) x 2 k-halves x 4 segments (128 steps).

#define BATCH 128
#define TLEN  512
#define CH    8
#define NSTEP (TLEN - 1)     // 511
#define NSEG  4
#define SEGLEN 128           // seg 3: 127 real steps + 1 zero pad
#define SEGSZ  (SEGLEN * CH + 8)   // 1032 floats; pad absorbs prefetch
#define OUT_STRIDE 4680
#define OFF_L2 8
#define OFF_L3 72
#define OFF_L4 584

#define C3F (1.0f / 6.0f)
#define C4F (1.0f / 24.0f)

typedef unsigned long long u64;

__device__ __forceinline__ u64 ffma2(u64 a, u64 b, u64 c) {
    u64 d; asm("fma.rn.f32x2 %0, %1, %2, %3;" : "=l"(d) : "l"(a), "l"(b), "l"(c)); return d;
}
#define FFMA2_ACC(acc, a, b) \
    asm("fma.rn.f32x2 %0, %1, %2, %0;" : "+l"(acc) : "l"(a), "l"(b))
#define FADD2_ACC(acc, a) \
    asm("add.rn.f32x2 %0, %0, %1;" : "+l"(acc) : "l"(a))

__device__ __forceinline__ u64 pack2(float x, float y) {
    u64 d; asm("mov.b64 %0, {%1, %2};" : "=l"(d) : "f"(x), "f"(y)); return d;
}
__device__ __forceinline__ void unpack2(u64 a, float& x, float& y) {
    asm("mov.b64 {%0, %1}, %2;" : "=f"(x), "=f"(y) : "l"(a));
}

__global__ void __launch_bounds__(512, 1)
logsig_kernel(const float* __restrict__ path, float* __restrict__ out)
{
    __shared__ __align__(16) float s_dx[NSEG * SEGSZ];   // ~16.5 KB padded
    __shared__ __align__(16) float sL[NSEG][584];        // per-seg levels 1..3

    const int b   = blockIdx.x;
    const int tid = threadIdx.x;
    const float* p = path + (size_t)b * TLEN * CH;

    // zero the 4 segment pads (8 floats each)
    if (tid < 32)
        s_dx[(tid >> 3) * SEGSZ + SEGLEN * CH + (tid & 7)] = 0.0f;
    // increments into padded layout (global step 511 zero-padded)
    for (int idx = tid; idx < NSEG * SEGLEN * CH; idx += 512) {
        const int t = idx >> 3;            // global step
        const int c = idx & 7;
        float v = 0.0f;
        if (t < NSTEP) v = p[idx + CH] - p[idx];
        s_dx[(t >> 7) * SEGSZ + (t & 127) * CH + c] = v;
    }
    __syncthreads();

    const int s  = tid & 3;            // segment (lane bits 0..1: shfl tree)
    const int kh = (tid >> 2) & 1;     // k half
    const int ij = tid >> 3;           // 0..63
    const int i  = ij >> 3;
    const int j  = ij & 7;
    const int k0 = kh << 2;            // first owned k row

    u64 a2[4][4];                      // L4 rows k0..k0+3, l packed in pairs
    u64 r301 = 0, r323 = 0;            // r3 as k-pairs
    float r1 = 0.0f, r2 = 0.0f;
    #pragma unroll
    for (int kk = 0; kk < 4; ++kk)
        #pragma unroll
        for (int lp = 0; lp < 4; ++lp) a2[kk][lp] = 0;

    // ---- scan own segment (all loads prefetched one iteration ahead) ----
    {
        const float* d = &s_dx[s * SEGSZ];
        ulonglong2 qa = *(const ulonglong2*)(d);
        ulonglong2 qb = *(const ulonglong2*)(d + 4);
        float di = d[i];
        float dj = d[j];

        #pragma unroll 1
        for (int t = 0; t < SEGLEN; ++t, d += CH) {
            // prefetch next row (segment pad absorbs final over-read)
            const ulonglong2 nqa = *(const ulonglong2*)(d + CH);
            const ulonglong2 nqb = *(const ulonglong2*)(d + CH + 4);
            const float ndi = d[CH + i];
            const float ndj = d[CH + j];

            const float didj = di * dj;
            const float r1dj = r1 * dj;

            float ng = 0.5f * r2;
            ng = fmaf(C3F, r1dj, ng);
            ng = fmaf(C4F, didj, ng);
            float n2 = fmaf(0.5f, r1dj, r2);
            n2 = fmaf(C3F, didj, n2);
            const u64 ng2 = pack2(ng, ng);
            const u64 n22 = pack2(n2, n2);

            // own dk pairs straight from qa/qb (kh-select, alu pipe)
            const u64 dk01 = kh ? qb.x : qa.x;
            const u64 dk23 = kh ? qb.y : qa.y;

            const u64 g01 = ffma2(ng2, dk01, r301);
            const u64 g23 = ffma2(ng2, dk23, r323);
            FFMA2_ACC(r301, n22, dk01);
            FFMA2_ACC(r323, n22, dk23);

            float g0, g1, g2v, g3;
            unpack2(g01, g0, g1);
            unpack2(g23, g2v, g3);
            const u64 G0 = pack2(g0, g0);
            const u64 G1 = pack2(g1, g1);
            const u64 G2 = pack2(g2v, g2v);
            const u64 G3 = pack2(g3, g3);

            FFMA2_ACC(a2[0][0], G0, qa.x);  FFMA2_ACC(a2[0][1], G0, qa.y);
            FFMA2_ACC(a2[0][2], G0, qb.x);  FFMA2_ACC(a2[0][3], G0, qb.y);
            FFMA2_ACC(a2[1][0], G1, qa.x);  FFMA2_ACC(a2[1][1], G1, qa.y);
            FFMA2_ACC(a2[1][2], G1, qb.x);  FFMA2_ACC(a2[1][3], G1, qb.y);
            FFMA2_ACC(a2[2][0], G2, qa.x);  FFMA2_ACC(a2[2][1], G2, qa.y);
            FFMA2_ACC(a2[2][2], G2, qb.x);  FFMA2_ACC(a2[2][3], G2, qb.y);
            FFMA2_ACC(a2[3][0], G3, qa.x);  FFMA2_ACC(a2[3][1], G3, qa.y);
            FFMA2_ACC(a2[3][2], G3, qb.x);  FFMA2_ACC(a2[3][3], G3, qb.y);

            r2 = fmaf(0.5f, didj, r1dj) + r2;
            r1 += di;

            qa = nqa; qb = nqb; di = ndi; dj = ndj;
        }
    }

    // unpack r3 pairs to scalars for the tree/tail
    float r3[4];
    unpack2(r301, r3[0], r3[1]);
    unpack2(r323, r3[2], r3[3]);

    // ---- publish own segment levels 1..3 ----
    auto publish = [&](void) {
        #pragma unroll
        for (int kk = 0; kk < 4; ++kk) sL[s][72 + ij * 8 + k0 + kk] = r3[kk];
        if (kh == 0) sL[s][8 + ij] = r2;
        if (j == 0 && kh == 0) sL[s][i] = r1;
    };
    publish();
    __syncthreads();

    // ---- 2-round Chen combine tree over segments ----
    #pragma unroll 1
    for (int r = 0; r < 2; ++r) {
        const int blk   = 1 << r;
        const int Abase = s & ~((blk << 1) - 1);
        const int Bbase = Abase + blk;
        const float* LA = sL[Abase];
        const float* LB = sL[Bbase];

        const float A1 = LA[i];
        const float A2 = LA[8 + ij];
        float A3k[4];
        #pragma unroll
        for (int kk = 0; kk < 4; ++kk) A3k[kk] = LA[72 + ij * 8 + k0 + kk];

        const float c1  = A1 + LB[i];
        const float c2v = A2 + LB[8 + ij] + A1 * LB[j];

        float c3[4];
        #pragma unroll
        for (int kk = 0; kk < 4; ++kk) {
            const int k = k0 + kk;
            float t = A3k[kk] + LB[72 + ij * 8 + k];
            t = fmaf(A1, LB[8 + j * 8 + k], t);
            t = fmaf(A2, LB[k], t);
            c3[kk] = t;
        }

        const u64 A1d = pack2(A1, A1);
        const u64 A2d = pack2(A2, A2);
        const u64* b1p = (const u64*)&LB[0];

        #pragma unroll
        for (int kk = 0; kk < 4; ++kk) {
            const int k = k0 + kk;
            const u64* b3p = (const u64*)&LB[72 + (j * 8 + k) * 8];
            const u64* b2p = (const u64*)&LB[8 + k * 8];
            const u64 A3d = pack2(A3k[kk], A3k[kk]);
            #pragma unroll
            for (int lp = 0; lp < 4; ++lp) {
                u64 t = a2[kk][lp];
                const u64 part = __shfl_xor_sync(0xffffffffu, t, blk);
                FADD2_ACC(t, part);
                FFMA2_ACC(t, A1d, b3p[lp]);
                FFMA2_ACC(t, A2d, b2p[lp]);
                FFMA2_ACC(t, A3d, b1p[lp]);
                a2[kk][lp] = t;
            }
        }

        r1 = c1;
        r2 = c2v;
        #pragma unroll
        for (int kk = 0; kk < 4; ++kk) r3[kk] = c3[kk];

        __syncthreads();
        publish();
        __syncthreads();
    }

    // ---- closed-form log(1+x) truncated at depth 4 ----
    const float* L = sL[0];                 // final combined (all slots equal)
    const u64* v12 = (const u64*)L;         // L1 as packed pairs
    const float si = L[i];
    const float sj = L[j];
    const float sisj = si * sj;
    const float Qs = fmaf(1.0f / 3.0f, sisj, -0.5f * r2);
    const float Rs = -0.5f * si;
    const u64 Q2 = pack2(Qs, Qs);
    const u64 R2 = pack2(Rs, Rs);

    float* ob = out + (size_t)b * OUT_STRIDE;

    #pragma unroll
    for (int kk = 0; kk < 4; ++kk) {
        const int k = k0 + kk;
        const float sk = L[k];
        const float s2jk = L[8 + j * 8 + k];
        const float cross = fmaf(si, s2jk, r2 * sk);
        const float sss = sisj * sk;
        const float P = fmaf(1.0f / 3.0f, cross, -0.5f * r3[kk]) - 0.25f * sss;
        const float o3 = fmaf(1.0f / 3.0f, sss, fmaf(-0.5f, cross, r3[kk]));
        const u64 P2 = pack2(P, P);

        const u64* s2p = (const u64*)&L[8 + k * 8];
        const u64* s3p = (const u64*)&L[72 + (j * 8 + k) * 8];

        u64 ov[4];
        #pragma unroll
        for (int lp = 0; lp < 4; ++lp) {
            u64 t = a2[kk][lp];
            FFMA2_ACC(t, P2, v12[lp]);
            FFMA2_ACC(t, Q2, s2p[lp]);
            FFMA2_ACC(t, R2, s3p[lp]);
            ov[lp] = t;
        }

        if (kk == s) {          // replica s stores its matching row
            ulonglong2 w0 = {ov[0], ov[1]};
            ulonglong2 w1 = {ov[2], ov[3]};
            *(ulonglong2*)(&ob[OFF_L4 + (ij * 8 + k) * 8])     = w0;
            *(ulonglong2*)(&ob[OFF_L4 + (ij * 8 + k) * 8 + 4]) = w1;
            ob[OFF_L3 + ij * 8 + k] = o3;
        }
    }

    if (s == 0 && kh == 0)
        ob[OFF_L2 + ij] = fmaf(-0.5f, sisj, r2);
    if (s == 0 && kh == 0 && j == 0)
        ob[i] = r1;
}

extern "C" void kernel_launch(void* const* d_in, const int* in_sizes, int n_in,
                              void* d_out, int out_size)
{
    const float* path = (const float*)d_in[0];
    float* out = (float*)d_out;
    logsig_kernel<<<BATCH, 512>>>(path, out);
}